// round 4
// baseline (speedup 1.0000x reference)
#include <cuda_runtime.h>

// Problem constants (static per reference)
#define BSZ   128
#define NTOT  129
#define NPT   128          // N
#define GS    16
#define CH    384          // channels
#define CH4   96           // CH / 4
#define EPSW  0.05f
#define RMSEPS 1e-6f

__global__ __launch_bounds__(96, 21)
void K_Rectify_38216619000515_kernel(
    const float* __restrict__ f,        // (B, NTOT, CH)
    const float* __restrict__ distance, // (B, N, GS)
    const float* __restrict__ rf,       // (NTOT, CH)
    const float* __restrict__ knorm_w,  // (CH,)
    const int*   __restrict__ idx,      // (B, N, GS), int32, values in [0, B*N)
    float*       __restrict__ out)      // (B, NTOT, CH)
{
    const int bn  = blockIdx.x;      // 0 .. B*N-1
    const int b   = bn >> 7;         // N == 128
    const int n   = bn & 127;
    const int tid = threadIdx.x;     // 0..95, all lanes active

    __shared__ float sw[GS];         // raw weights 1/(d+eps)
    __shared__ int   soff[GS];       // gathered row offset in float4 units
    __shared__ float red[3];

    if (tid < GS) {
        float d = distance[bn * GS + tid];
        sw[tid] = 1.0f / (d + EPSW);
        int r = idx[bn * GS + tid] & (BSZ * NPT - 1);  // mask: crash-proof, no-op for valid data
        int rb = r >> 7;                  // r / N
        int rn = r & 127;                 // r % N
        soff[tid] = (rb * NTOT + rn + 1) * CH4;  // row offset in float4 units (fits int32)
    }

    // cls token passthrough: out[b,0,:] = f[b,0,:]  (96 lanes == CH4 float4s)
    if (n == 0) {
        const float4* src = (const float4*)f + b * (NTOT * CH4);
        float4*       dst = (float4*)out     + b * (NTOT * CH4);
        dst[tid] = src[tid];
    }
    __syncthreads();

    // every thread computes sum of weights (16 shared broadcast reads, cheap)
    float wsum = 0.0f;
#pragma unroll
    for (int g = 0; g < GS; ++g) wsum += sw[g];
    const float invw = 1.0f / wsum;

    const int xrow4 = (b * NTOT + 1 + n) * CH4;   // x row offset in float4 units
    const float4* f4 = (const float4*)f;

    // 16 independent coalesced float4 gathers; full unroll for MLP
    float4 sf = make_float4(0.f, 0.f, 0.f, 0.f);
#pragma unroll
    for (int g = 0; g < GS; ++g) {
        const float4 v = __ldg(f4 + soff[g] + tid);
        const float wg = sw[g];
        sf.x = fmaf(wg, v.x, sf.x);
        sf.y = fmaf(wg, v.y, sf.y);
        sf.z = fmaf(wg, v.z, sf.z);
        sf.w = fmaf(wg, v.w, sf.w);
    }
    const float4 xv = __ldg(f4 + xrow4 + tid);
    // sf = (sum w*row)/W - x     (valid because reference normalizes w, sum=1)
    sf.x = sf.x * invw - xv.x;
    sf.y = sf.y * invw - xv.y;
    sf.z = sf.z * invw - xv.z;
    sf.w = sf.w * invw - xv.w;
    float local = sf.x * sf.x + sf.y * sf.y + sf.z * sf.z + sf.w * sf.w;

    // block reduction of sum(sf^2): warp shuffle + shared across 3 warps
#pragma unroll
    for (int off = 16; off > 0; off >>= 1)
        local += __shfl_down_sync(0xffffffffu, local, off);
    if ((tid & 31) == 0) red[tid >> 5] = local;
    __syncthreads();
    const float total = red[0] + red[1] + red[2];

    const float rinv = rsqrtf(total * (1.0f / CH) + RMSEPS);

    const float4 rv = __ldg((const float4*)rf + (1 + n) * CH4 + tid);
    const float4 kv = __ldg((const float4*)knorm_w + tid);
    float4 o;
    o.x = rv.x + xv.x + sf.x * rinv * kv.x;
    o.y = rv.y + xv.y + sf.y * rinv * kv.y;
    o.z = rv.z + xv.z + sf.z * rinv * kv.z;
    o.w = rv.w + xv.w + sf.w * rinv * kv.w;
    ((float4*)out)[xrow4 + tid] = o;
}

extern "C" void kernel_launch(void* const* d_in, const int* in_sizes, int n_in,
                              void* d_out, int out_size)
{
    const float* f        = (const float*)d_in[0];
    const float* distance = (const float*)d_in[1];
    const float* rf       = (const float*)d_in[2];
    const float* knorm_w  = (const float*)d_in[3];
    const int*   idx      = (const int*)d_in[4];
    float*       out      = (float*)d_out;

    K_Rectify_38216619000515_kernel<<<BSZ * NPT, 96>>>(
        f, distance, rf, knorm_w, idx, out);
}

// round 5
// speedup vs baseline: 1.1115x; 1.1115x over previous
#include <cuda_runtime.h>

// Problem constants (static per reference)
#define BSZ   128
#define NTOT  129
#define NPT   128          // N
#define GS    16
#define CH    384          // channels
#define CH4   96           // CH / 4
#define EPSW  0.05f
#define RMSEPS 1e-6f

__global__ __launch_bounds__(128, 16)
void K_Rectify_38216619000515_kernel(
    const float* __restrict__ f,        // (B, NTOT, CH)
    const float* __restrict__ distance, // (B, N, GS)
    const float* __restrict__ rf,       // (NTOT, CH)
    const float* __restrict__ knorm_w,  // (CH,)
    const int*   __restrict__ idx,      // (B, N, GS), int32, values in [0, B*N)
    float*       __restrict__ out)      // (B, NTOT, CH)
{
    const int bn   = blockIdx.x;      // 0 .. B*N-1
    const int b    = bn >> 7;         // N == 128
    const int n    = bn & 127;
    const int tid  = threadIdx.x;     // 0..127
    const int w    = tid >> 5;        // warp 0..3
    const int lane = tid & 31;

    __shared__ float2 sgw[GS];            // {row offset (as int bits), weight}
    __shared__ float  swsum;
    __shared__ float4 sacc[4][3][32];     // per-warp partial sums, 3 row-thirds
    __shared__ float4 sx[3][32];          // raw x row
    __shared__ float  red[3];

    if (tid < GS) {
        float d  = distance[bn * GS + tid];
        float wt = 1.0f / (d + EPSW);
        int r  = idx[bn * GS + tid] & (BSZ * NPT - 1);
        int off = ((r >> 7) * NTOT + (r & 127) + 1) * CH4;  // float4 units
        sgw[tid] = make_float2(__int_as_float(off), wt);
        // wsum: reduce across lanes 0..15 of warp 0
        float s = wt;
        s += __shfl_down_sync(0x0000ffffu, s, 8);
        s += __shfl_down_sync(0x0000ffffu, s, 4);
        s += __shfl_down_sync(0x0000ffffu, s, 2);
        s += __shfl_down_sync(0x0000ffffu, s, 1);
        if (tid == 0) swsum = s;
    }

    // cls token passthrough: out[b,0,:] = f[b,0,:]
    if (n == 0 && tid < CH4) {
        const float4* src = (const float4*)f + b * (NTOT * CH4);
        float4*       dst = (float4*)out     + b * (NTOT * CH4);
        dst[tid] = src[tid];
    }
    __syncthreads();

    const float4* f4    = (const float4*)f;
    const int     xrow4 = (b * NTOT + 1 + n) * CH4;

    // each warp: 4 gather rows x 3 thirds (static accumulators, 12 LDG.128/thread)
    float4 a0 = make_float4(0.f,0.f,0.f,0.f);
    float4 a1 = make_float4(0.f,0.f,0.f,0.f);
    float4 a2 = make_float4(0.f,0.f,0.f,0.f);
    const int gbase = w << 2;
#pragma unroll
    for (int r = 0; r < 4; ++r) {
        const float2 gw = sgw[gbase + r];
        const int   off = __float_as_int(gw.x);
        const float wt  = gw.y;
        const float4 v0 = __ldg(f4 + off +  0 + lane);
        const float4 v1 = __ldg(f4 + off + 32 + lane);
        const float4 v2 = __ldg(f4 + off + 64 + lane);
        a0.x = fmaf(wt, v0.x, a0.x); a0.y = fmaf(wt, v0.y, a0.y);
        a0.z = fmaf(wt, v0.z, a0.z); a0.w = fmaf(wt, v0.w, a0.w);
        a1.x = fmaf(wt, v1.x, a1.x); a1.y = fmaf(wt, v1.y, a1.y);
        a1.z = fmaf(wt, v1.z, a1.z); a1.w = fmaf(wt, v1.w, a1.w);
        a2.x = fmaf(wt, v2.x, a2.x); a2.y = fmaf(wt, v2.y, a2.y);
        a2.z = fmaf(wt, v2.z, a2.z); a2.w = fmaf(wt, v2.w, a2.w);
    }
    sacc[w][0][lane] = a0;
    sacc[w][1][lane] = a1;
    sacc[w][2][lane] = a2;
    if (w < 3) {
        sx[w][lane] = __ldg(f4 + xrow4 + (w << 5) + lane);
    }
    __syncthreads();

    // epilogue: threads 0..95 (whole warps 0..2) own one float4 channel-group each
    float4 sf = make_float4(0.f,0.f,0.f,0.f);
    float4 xv = make_float4(0.f,0.f,0.f,0.f);
    float  local = 0.0f;
    if (tid < CH4) {
        const int s  = tid >> 5;
        const int ln = tid & 31;
        const float4 p0 = sacc[0][s][ln];
        const float4 p1 = sacc[1][s][ln];
        const float4 p2 = sacc[2][s][ln];
        const float4 p3 = sacc[3][s][ln];
        const float invw = 1.0f / swsum;
        xv = sx[s][ln];
        sf.x = (p0.x + p1.x + p2.x + p3.x) * invw - xv.x;
        sf.y = (p0.y + p1.y + p2.y + p3.y) * invw - xv.y;
        sf.z = (p0.z + p1.z + p2.z + p3.z) * invw - xv.z;
        sf.w = (p0.w + p1.w + p2.w + p3.w) * invw - xv.w;
        local = sf.x*sf.x + sf.y*sf.y + sf.z*sf.z + sf.w*sf.w;
    }
#pragma unroll
    for (int off = 16; off > 0; off >>= 1)
        local += __shfl_down_sync(0xffffffffu, local, off);
    if (lane == 0 && w < 3) red[w] = local;
    __syncthreads();
    const float total = red[0] + red[1] + red[2];
    const float rinv  = rsqrtf(total * (1.0f / CH) + RMSEPS);

    if (tid < CH4) {
        const float4 rv = __ldg((const float4*)rf + (1 + n) * CH4 + tid);
        const float4 kv = __ldg((const float4*)knorm_w + tid);
        float4 o;
        o.x = rv.x + xv.x + sf.x * rinv * kv.x;
        o.y = rv.y + xv.y + sf.y * rinv * kv.y;
        o.z = rv.z + xv.z + sf.z * rinv * kv.z;
        o.w = rv.w + xv.w + sf.w * rinv * kv.w;
        ((float4*)out)[xrow4 + tid] = o;
    }
}

extern "C" void kernel_launch(void* const* d_in, const int* in_sizes, int n_in,
                              void* d_out, int out_size)
{
    const float* f        = (const float*)d_in[0];
    const float* distance = (const float*)d_in[1];
    const float* rf       = (const float*)d_in[2];
    const float* knorm_w  = (const float*)d_in[3];
    const int*   idx      = (const int*)d_in[4];
    float*       out      = (float*)d_out;

    K_Rectify_38216619000515_kernel<<<BSZ * NPT, 128>>>(
        f, distance, rf, knorm_w, idx, out);
}

// round 6
// speedup vs baseline: 1.4257x; 1.2827x over previous
#include <cuda_runtime.h>

// Problem constants (static per reference)
#define BSZ   128
#define NTOT  129
#define NPT   128          // N
#define GS    16
#define CH    384          // channels
#define CH4   96           // CH / 4
#define EPSW  0.05f
#define RMSEPS 1e-6f

__global__ __launch_bounds__(96, 12)
void K_Rectify_38216619000515_kernel(
    const float* __restrict__ f,        // (B, NTOT, CH)
    const float* __restrict__ distance, // (B, N, GS)
    const float* __restrict__ rf,       // (NTOT, CH)
    const float* __restrict__ knorm_w,  // (CH,)
    const int*   __restrict__ idx,      // (B, N, GS), int32, values in [0, B*N)
    float*       __restrict__ out)      // (B, NTOT, CH)
{
    const int bid = blockIdx.x;          // 0..8191, two points per block
    const int bn0 = bid << 1;
    const int bn1 = bn0 | 1;
    const int tid = threadIdx.x;         // 0..95
    const int w   = tid >> 5;
    const int lane = tid & 31;

    __shared__ float2 sgw[2][GS];        // {row offset (int bits), weight}
    __shared__ float  red[2][3];

    if (tid < 2 * GS) {
        const int p  = tid >> 4;         // point 0/1
        const int g  = tid & 15;
        const int bn = bn0 + p;
        float d  = distance[bn * GS + g];
        float wt = 1.0f / (d + EPSW);
        int r    = idx[bn * GS + g] & (BSZ * NPT - 1);
        int off  = ((r >> 7) * NTOT + (r & 127) + 1) * CH4;   // float4 units
        sgw[p][g] = make_float2(__int_as_float(off), wt);
    }

    const int b0 = bn0 >> 7, n0 = bn0 & 127;
    const int b1 = bn1 >> 7, n1 = bn1 & 127;   // n1 is odd -> never 0

    // cls token passthrough (only point A can have n==0); 96 lanes == CH4
    if (n0 == 0) {
        ((float4*)out)[b0 * (NTOT * CH4) + tid] =
            __ldg((const float4*)f + b0 * (NTOT * CH4) + tid);
    }
    __syncthreads();

    float wsumA = 0.0f, wsumB = 0.0f;
#pragma unroll
    for (int g = 0; g < GS; ++g) { wsumA += sgw[0][g].y; wsumB += sgw[1][g].y; }
    const float invwA = 1.0f / wsumA;
    const float invwB = 1.0f / wsumB;

    const float4* f4 = (const float4*)f;
    const int xrowA = (b0 * NTOT + 1 + n0) * CH4;
    const int xrowB = (b1 * NTOT + 1 + n1) * CH4;

    float4 sa = make_float4(0.f,0.f,0.f,0.f);
    float4 sb = make_float4(0.f,0.f,0.f,0.f);
#pragma unroll
    for (int g = 0; g < GS; ++g) {
        const float2 ga = sgw[0][g];
        const float2 gb = sgw[1][g];
        const float4 va = __ldg(f4 + __float_as_int(ga.x) + tid);
        const float4 vb = __ldg(f4 + __float_as_int(gb.x) + tid);
        const float wa = ga.y, wb = gb.y;
        sa.x = fmaf(wa, va.x, sa.x); sa.y = fmaf(wa, va.y, sa.y);
        sa.z = fmaf(wa, va.z, sa.z); sa.w = fmaf(wa, va.w, sa.w);
        sb.x = fmaf(wb, vb.x, sb.x); sb.y = fmaf(wb, vb.y, sb.y);
        sb.z = fmaf(wb, vb.z, sb.z); sb.w = fmaf(wb, vb.w, sb.w);
    }
    const float4 xa = __ldg(f4 + xrowA + tid);
    const float4 xb = __ldg(f4 + xrowB + tid);

    // (sum w*row)/W - x   (weights normalized in reference)
    sa.x = sa.x * invwA - xa.x;  sa.y = sa.y * invwA - xa.y;
    sa.z = sa.z * invwA - xa.z;  sa.w = sa.w * invwA - xa.w;
    sb.x = sb.x * invwB - xb.x;  sb.y = sb.y * invwB - xb.y;
    sb.z = sb.z * invwB - xb.z;  sb.w = sb.w * invwB - xb.w;

    float lA = sa.x*sa.x + sa.y*sa.y + sa.z*sa.z + sa.w*sa.w;
    float lB = sb.x*sb.x + sb.y*sb.y + sb.z*sb.z + sb.w*sb.w;

#pragma unroll
    for (int off = 16; off > 0; off >>= 1) {
        lA += __shfl_down_sync(0xffffffffu, lA, off);
        lB += __shfl_down_sync(0xffffffffu, lB, off);
    }
    if (lane == 0) { red[0][w] = lA; red[1][w] = lB; }
    __syncthreads();
    const float rinvA = rsqrtf((red[0][0] + red[0][1] + red[0][2]) * (1.0f / CH) + RMSEPS);
    const float rinvB = rsqrtf((red[1][0] + red[1][1] + red[1][2]) * (1.0f / CH) + RMSEPS);

    const float4 kv  = __ldg((const float4*)knorm_w + tid);
    const float4 rvA = __ldg((const float4*)rf + (1 + n0) * CH4 + tid);
    const float4 rvB = __ldg((const float4*)rf + (1 + n1) * CH4 + tid);

    float4 oA, oB;
    oA.x = rvA.x + xa.x + sa.x * rinvA * kv.x;
    oA.y = rvA.y + xa.y + sa.y * rinvA * kv.y;
    oA.z = rvA.z + xa.z + sa.z * rinvA * kv.z;
    oA.w = rvA.w + xa.w + sa.w * rinvA * kv.w;
    oB.x = rvB.x + xb.x + sb.x * rinvB * kv.x;
    oB.y = rvB.y + xb.y + sb.y * rinvB * kv.y;
    oB.z = rvB.z + xb.z + sb.z * rinvB * kv.z;
    oB.w = rvB.w + xb.w + sb.w * rinvB * kv.w;
    ((float4*)out)[xrowA + tid] = oA;
    ((float4*)out)[xrowB + tid] = oB;
}

extern "C" void kernel_launch(void* const* d_in, const int* in_sizes, int n_in,
                              void* d_out, int out_size)
{
    const float* f        = (const float*)d_in[0];
    const float* distance = (const float*)d_in[1];
    const float* rf       = (const float*)d_in[2];
    const float* knorm_w  = (const float*)d_in[3];
    const int*   idx      = (const int*)d_in[4];
    float*       out      = (float*)d_out;

    K_Rectify_38216619000515_kernel<<<(BSZ * NPT) / 2, 96>>>(
        f, distance, rf, knorm_w, idx, out);
}